// round 7
// baseline (speedup 1.0000x reference)
#include <cuda_runtime.h>
#include <cuda_bf16.h>
#include <math.h>

#define BB    8
#define CC    64
#define HEADS 4
#define CH    16
#define HH    256
#define WW    256
#define HW    (HH*WW)
#define EPS   1e-12f

typedef unsigned int u32;

// ---------------- static device scratch (no allocs allowed) ----------------
__device__ float g_q [BB*CC*HW];
__device__ float g_k [BB*CC*HW];
__device__ float g_v [BB*CC*HW];
__device__ float g_t0[BB*CC*HW];
__device__ float g_gram[BB*HEADS*CH*CH];
__device__ float g_qn[BB*CC];
__device__ float g_kn[BB*CC];
__device__ float g_attn[BB*HEADS*CH*CH];

// ---------------- zero the small accumulators (graph replays!) -------------
__global__ void k_zero_small() {
    int tid = threadIdx.x;
    for (int i = tid; i < BB*HEADS*CH*CH; i += 1024) { g_gram[i] = 0.f; g_attn[i] = 0.f; }
    for (int i = tid; i < BB*CC; i += 1024)          { g_qn[i] = 0.f;  g_kn[i] = 0.f; }
}

// ---------------- bf16 split + mma helpers ---------------------------------
__device__ __forceinline__ void split2pack(float v0, float v1, u32& H, u32& L) {
    __nv_bfloat16 h0 = __float2bfloat16(v0), h1 = __float2bfloat16(v1);
    float r0 = v0 - __bfloat162float(h0), r1 = v1 - __bfloat162float(h1);
    __nv_bfloat16 l0 = __float2bfloat16(r0), l1 = __float2bfloat16(r1);
    H = (u32)__bfloat16_as_ushort(h0) | ((u32)__bfloat16_as_ushort(h1) << 16);
    L = (u32)__bfloat16_as_ushort(l0) | ((u32)__bfloat16_as_ushort(l1) << 16);
}

__device__ __forceinline__ void mma16816(float* d, const u32* a, u32 b0, u32 b1) {
    asm volatile(
        "mma.sync.aligned.m16n8k16.row.col.f32.bf16.bf16.f32 "
        "{%0,%1,%2,%3}, {%4,%5,%6,%7}, {%8,%9}, {%0,%1,%2,%3};"
        : "+f"(d[0]), "+f"(d[1]), "+f"(d[2]), "+f"(d[3])
        : "r"(a[0]), "r"(a[1]), "r"(a[2]), "r"(a[3]), "r"(b0), "r"(b1));
}

// ---------------- fused q,k,v 1x1 convs (fp32 scalar) -----------------------
__device__ __forceinline__ void conv1x1_px(const float* src, const float* swp,
                                           const float* bglob, float* dst) {
    float acc[64];
#pragma unroll
    for (int oc = 0; oc < 64; oc++) acc[oc] = __ldg(&bglob[oc]);
#pragma unroll 2
    for (int i = 0; i < 64; i++) {
        float xi = src[i*HW];
        const float4* w4 = reinterpret_cast<const float4*>(swp + i*64);
#pragma unroll
        for (int o4 = 0; o4 < 16; o4++) {
            float4 w = w4[o4];
            acc[o4*4+0] += w.x*xi; acc[o4*4+1] += w.y*xi;
            acc[o4*4+2] += w.z*xi; acc[o4*4+3] += w.w*xi;
        }
    }
#pragma unroll
    for (int oc = 0; oc < 64; oc++) dst[oc*HW] = acc[oc];
}

__global__ void k_qkv(const float* __restrict__ x,  const float* __restrict__ y,
                      const float* __restrict__ qw, const float* __restrict__ qb,
                      const float* __restrict__ kw, const float* __restrict__ kb,
                      const float* __restrict__ vw, const float* __restrict__ vb) {
    __shared__ __align__(16) float sw[3*64*64];      // transposed [i][oc]
    int tid = threadIdx.x;
    for (int idx = tid; idx < 64*64; idx += 256) {
        int oc = idx >> 6, i = idx & 63;
        sw[0*4096 + i*64 + oc] = qw[idx];
        sw[1*4096 + i*64 + oc] = kw[idx];
        sw[2*4096 + i*64 + oc] = vw[idx];
    }
    __syncthreads();
    int b  = blockIdx.y;
    int px = blockIdx.x*256 + tid;
    const float* xb = x + (size_t)b*CC*HW + px;
    const float* yb = y + (size_t)b*CC*HW + px;
    float* qo = g_q + (size_t)b*CC*HW + px;
    float* ko = g_k + (size_t)b*CC*HW + px;
    float* vo = g_v + (size_t)b*CC*HW + px;
    conv1x1_px(xb, sw + 0*4096, qb, qo);
    conv1x1_px(yb, sw + 1*4096, kb, ko);
    conv1x1_px(yb, sw + 2*4096, vb, vo);
}

// ---------------- Gram matrices + row norms (fused reduction) --------------
__global__ void k_gram() {
    __shared__ float qs[16*65];
    __shared__ float ks[16*65];
    int tid = threadIdx.x;
    int c = tid & 15, d = tid >> 4;
    int bh = blockIdx.y, b = bh >> 2, h = bh & 3;
    const float* qp = g_q + ((size_t)b*CC + h*CH)*HW;
    const float* kp = g_k + ((size_t)b*CC + h*CH)*HW;
    float acc = 0.f, nacc = 0.f;
    for (int t = 0; t < 32; t++) {
        int n0 = blockIdx.x*2048 + t*64;
        for (int idx = tid; idx < 1024; idx += 256) {
            int r = idx >> 6, j = idx & 63;
            qs[r*65 + j] = qp[(size_t)r*HW + n0 + j];
            ks[r*65 + j] = kp[(size_t)r*HW + n0 + j];
        }
        __syncthreads();
#pragma unroll 8
        for (int j = 0; j < 64; j++) acc += qs[c*65 + j] * ks[d*65 + j];
        if (d == 0) {
#pragma unroll 8
            for (int j = 0; j < 64; j++) { float v = qs[c*65 + j]; nacc += v*v; }
        } else if (d == 1) {
#pragma unroll 8
            for (int j = 0; j < 64; j++) { float v = ks[c*65 + j]; nacc += v*v; }
        }
        __syncthreads();
    }
    atomicAdd(&g_gram[bh*256 + c*16 + d], acc);
    if (d == 0) atomicAdd(&g_qn[b*CC + h*CH + c], nacc);
    if (d == 1) atomicAdd(&g_kn[b*CC + h*CH + c], nacc);
}

// ---------------- softmax over d (tiny) ------------------------------------
__global__ void k_softmax() {
    int tid = threadIdx.x;              // 512 = 32 bh * 16 rows
    int bh = tid >> 4, c = tid & 15;
    int b = bh >> 2, h = bh & 3;
    float nq = fmaxf(sqrtf(g_qn[b*CC + h*CH + c]), EPS);
    float l[16], m = -1e30f;
#pragma unroll
    for (int d = 0; d < 16; d++) {
        float nk = fmaxf(sqrtf(g_kn[b*CC + h*CH + d]), EPS);
        l[d] = g_gram[bh*256 + c*16 + d] / (nq * nk);
        m = fmaxf(m, l[d]);
    }
    float s = 0.f;
#pragma unroll
    for (int d = 0; d < 16; d++) { l[d] = expf(l[d] - m); s += l[d]; }
    float inv = 1.f / s;
#pragma unroll
    for (int d = 0; d < 16; d++) g_attn[bh*256 + c*16 + d] = l[d] * inv;
}

// ---------------- out = attn @ v -------------------------------------------
__global__ void k_apply() {
    __shared__ __align__(16) float sa[HEADS*CH*CH];   // 1024 floats
    int tid = threadIdx.x;
    int b = blockIdx.y;
    for (int i = tid; i < 1024; i += 256) sa[i] = g_attn[b*1024 + i];
    __syncthreads();
    int px = blockIdx.x*256 + tid;
    const float* vb = g_v  + (size_t)b*CC*HW + px;
    float*       ob = g_t0 + (size_t)b*CC*HW + px;
#pragma unroll
    for (int h = 0; h < 4; h++) {
        float vr[16];
#pragma unroll
        for (int d = 0; d < 16; d++) vr[d] = vb[(size_t)(h*CH + d)*HW];
#pragma unroll
        for (int c = 0; c < 16; c++) {
            const float4* a4 = reinterpret_cast<const float4*>(sa + h*256 + c*16);
            float s = 0.f;
#pragma unroll
            for (int d4 = 0; d4 < 4; d4++) {
                float4 a = a4[d4];
                s += a.x*vr[d4*4+0] + a.y*vr[d4*4+1] + a.z*vr[d4*4+2] + a.w*vr[d4*4+3];
            }
            ob[(size_t)(h*CH + c)*HW] = s;
        }
    }
}

// ---------------- 3x3 conv via bf16-split mma.sync -------------------------
// Block 256 thr = 8 warps (4 m-warps x 2 n-warps). Output tile: 64 oc x 128 px
// (32w x 4h spatial). K = 9 taps x 64 ic, chunked 16 ic; tap-major im2col:
// B-frag = LDS of the resident input tile at tap-shifted address.
// smem (dynamic, u32):
//   sInH/sInL : [8 icp][6 y][34 x]            (1632 each)
//   sWH/sWL   : [9 tap][8 icp][64 m pad 72]   (5184 each)
#define IN_TILE  1632
#define W_TILE   5184
#define W_STRIDE 72
#define SMEM_U32 (2*IN_TILE + 2*W_TILE)

__global__ void __launch_bounds__(256) k_conv3mma(
        const float* __restrict__ in, const float* __restrict__ w,
        const float* __restrict__ bias, const float* __restrict__ skip,
        const float* __restrict__ skip2, float* __restrict__ out, int do_relu) {
    extern __shared__ u32 S[];
    u32* sInH = S;
    u32* sInL = S + IN_TILE;
    u32* sWH  = S + 2*IN_TILE;
    u32* sWL  = S + 2*IN_TILE + W_TILE;

    int tid  = threadIdx.x;
    int lane = tid & 31, wid = tid >> 5;
    int wm = wid & 3, wn = wid >> 2;            // warp m-band, n-half
    int t4 = lane & 3, g8 = lane >> 2;
    int b   = blockIdx.z;
    int gx0 = blockIdx.x * 32, gy0 = blockIdx.y * 4;
    const float* inb = in + (size_t)b*CC*HW;

    float acc[8][4];
#pragma unroll
    for (int j = 0; j < 8; j++)
#pragma unroll
        for (int r = 0; r < 4; r++) acc[j][r] = 0.f;

    // per-thread B base offsets (one per n-tile j)
    int pbase[8];
#pragma unroll
    for (int j = 0; j < 8; j++) {
        int p  = wn*64 + j*8 + g8;              // pixel index in 128-px tile
        int py = p >> 5, px = p & 31;
        pbase[j] = t4*204 + py*34 + px;         // icp=t4, y=py, x=px (halo base)
    }
    int abase = t4*W_STRIDE + wm*16 + g8;

    for (int icb = 0; icb < 64; icb += 16) {
        // ---- input tile (split hi/lo, ic-pairs packed) ----
        for (int idx = tid; idx < IN_TILE; idx += 256) {
            int icp = idx / 204;
            int r   = idx % 204;
            int yy  = r / 34, xx = r % 34;
            int gy = gy0 + yy - 1, gx = gx0 + xx - 1;
            float v0 = 0.f, v1 = 0.f;
            if (gy >= 0 && gy < HH && gx >= 0 && gx < WW) {
                const float* p = inb + (size_t)(icb + 2*icp)*HW + gy*WW + gx;
                v0 = p[0]; v1 = p[HW];
            }
            u32 H, L; split2pack(v0, v1, H, L);
            sInH[idx] = H; sInL[idx] = L;
        }
        // ---- weight slab: [tap][icp][m] ----
        for (int idx = tid; idx < 9*8*64; idx += 256) {
            int tap = idx >> 9;                 // /512
            int r   = idx & 511;
            int icp = r >> 6, m = r & 63;
            const float* wp = w + (size_t)m*576 + (size_t)(icb + 2*icp)*9 + tap;
            u32 H, L; split2pack(wp[0], wp[9], H, L);
            int o = (tap*8 + icp)*W_STRIDE + m;
            sWH[o] = H; sWL[o] = L;
        }
        __syncthreads();

#pragma unroll 3
        for (int tap = 0; tap < 9; tap++) {
            int dyx = (tap/3)*34 + (tap%3);
            int ab = tap*(8*W_STRIDE) + abase;
            u32 aH[4], aL[4];
            aH[0] = sWH[ab];                aH[1] = sWH[ab + 8];
            aH[2] = sWH[ab + 4*W_STRIDE];   aH[3] = sWH[ab + 4*W_STRIDE + 8];
            aL[0] = sWL[ab];                aL[1] = sWL[ab + 8];
            aL[2] = sWL[ab + 4*W_STRIDE];   aL[3] = sWL[ab + 4*W_STRIDE + 8];
#pragma unroll
            for (int j = 0; j < 8; j++) {
                int bo = pbase[j] + dyx;
                u32 bH0 = sInH[bo], bH1 = sInH[bo + 4*204];
                u32 bL0 = sInL[bo], bL1 = sInL[bo + 4*204];
                mma16816(acc[j], aH, bH0, bH1);
                mma16816(acc[j], aH, bL0, bL1);
                mma16816(acc[j], aL, bH0, bH1);
            }
        }
        __syncthreads();
    }

    // ---- epilogue: bias, relu, skips, store (float2 per m-row) ----
#pragma unroll
    for (int j = 0; j < 8; j++) {
        int p  = wn*64 + j*8 + 2*t4;
        int py = p >> 5, px = p & 31;
        size_t rowidx = (size_t)b*CC*HW + (size_t)(gy0+py)*WW + gx0 + px;
#pragma unroll
        for (int mh = 0; mh < 2; mh++) {
            int oc = wm*16 + g8 + mh*8;
            size_t idx = rowidx + (size_t)oc*HW;
            float v0 = acc[j][mh*2+0] + __ldg(&bias[oc]);
            float v1 = acc[j][mh*2+1] + __ldg(&bias[oc]);
            if (do_relu) { v0 = fmaxf(v0, 0.f); v1 = fmaxf(v1, 0.f); }
            if (skip)  { v0 += skip[idx];  v1 += skip[idx+1]; }
            if (skip2) { v0 += skip2[idx]; v1 += skip2[idx+1]; }
            *reinterpret_cast<float2*>(&out[idx]) = make_float2(v0, v1);
        }
    }
}

// ---------------- launcher ---------------------------------------------------
extern "C" void kernel_launch(void* const* d_in, const int* in_sizes, int n_in,
                              void* d_out, int out_size) {
    const float* x    = (const float*)d_in[0];
    const float* y    = (const float*)d_in[1];
    const float* qw   = (const float*)d_in[2];
    const float* qb   = (const float*)d_in[3];
    const float* kw   = (const float*)d_in[4];
    const float* kb   = (const float*)d_in[5];
    const float* vw   = (const float*)d_in[6];
    const float* vb   = (const float*)d_in[7];
    const float* r1w1 = (const float*)d_in[8];
    const float* r1b1 = (const float*)d_in[9];
    const float* r1w2 = (const float*)d_in[10];
    const float* r1b2 = (const float*)d_in[11];
    const float* r2w1 = (const float*)d_in[12];
    const float* r2b1 = (const float*)d_in[13];
    const float* r2w2 = (const float*)d_in[14];
    const float* r2b2 = (const float*)d_in[15];
    float* outp = (float*)d_out;

    float *pq, *pk, *pt0;
    cudaGetSymbolAddress((void**)&pq,  g_q);
    cudaGetSymbolAddress((void**)&pk,  g_k);
    cudaGetSymbolAddress((void**)&pt0, g_t0);

    static int smem_set = 0;
    int smem_bytes = SMEM_U32 * 4;
    if (!smem_set) {
        cudaFuncSetAttribute(k_conv3mma, cudaFuncAttributeMaxDynamicSharedMemorySize, smem_bytes);
        smem_set = 1;
    }

    k_zero_small<<<1, 1024>>>();
    k_qkv <<<dim3(HW/256, BB), 256>>>(x, y, qw, qb, kw, kb, vw, vb);
    k_gram<<<dim3(32, BB*HEADS), 256>>>();
    k_softmax<<<1, 512>>>();
    k_apply<<<dim3(HW/256, BB), 256>>>();

    dim3 cgrid(WW/32, HH/4, BB);
    // resblock 1: t0 -> q (relu conv1), q -> k (conv2 + t0 skip)
    k_conv3mma<<<cgrid, 256, smem_bytes>>>(pt0, r1w1, r1b1, nullptr, nullptr, pq, 1);
    k_conv3mma<<<cgrid, 256, smem_bytes>>>(pq,  r1w2, r1b2, pt0,     nullptr, pk, 0);
    // resblock 2: k -> q (relu conv1), q -> d_out (conv2 + k skip + y)
    k_conv3mma<<<cgrid, 256, smem_bytes>>>(pk,  r2w1, r2b1, nullptr, nullptr, pq, 1);
    k_conv3mma<<<cgrid, 256, smem_bytes>>>(pq,  r2w2, r2b2, pk,      y,       outp, 0);
}

// round 9
// speedup vs baseline: 2.8154x; 2.8154x over previous
#include <cuda_runtime.h>
#include <cuda_bf16.h>
#include <math.h>

#define BB 8
#define CC 64
#define HEADS 4
#define CH 16
#define HH 256
#define WW 256
#define HW (HH*WW)
#define EPS 1e-12f

typedef unsigned int u32;

// ---------------- static device scratch ----------------
__device__ float g_q [BB*CC*HW];
__device__ float g_k [BB*CC*HW];
__device__ float g_v [BB*CC*HW];
__device__ float g_t0[BB*CC*HW];
__device__ float g_gram[BB*HEADS*CH*CH];
__device__ float g_qn[BB*CC];
__device__ float g_kn[BB*CC];
__device__ __align__(16) u32 g_wbuf[4*9*64*64];   // tf32 weights [conv][tap][ic][oc]

__device__ __forceinline__ u32 to_tf32(float v) {
    u32 t; asm("cvt.rna.tf32.f32 %0, %1;" : "=r"(t) : "f"(v)); return t;
}
__device__ __forceinline__ void mma_tf32(float* d, u32 a0, u32 a1, u32 a2, u32 a3,
                                         u32 b0, u32 b1) {
    asm volatile(
        "mma.sync.aligned.m16n8k8.row.col.f32.tf32.tf32.f32 "
        "{%0,%1,%2,%3}, {%4,%5,%6,%7}, {%8,%9}, {%0,%1,%2,%3};"
        : "+f"(d[0]), "+f"(d[1]), "+f"(d[2]), "+f"(d[3])
        : "r"(a0), "r"(a1), "r"(a2), "r"(a3), "r"(b0), "r"(b1));
}

// ---------------- fused q,k,v 1x1 convs + accumulator zeroing ---------------
__device__ __forceinline__ void conv1x1_px(const float* src, const float* swp,
                                           const float* bglob, float* dst) {
    float acc[64];
#pragma unroll
    for (int oc = 0; oc < 64; oc++) acc[oc] = __ldg(&bglob[oc]);
#pragma unroll 2
    for (int i = 0; i < 64; i++) {
        float xi = src[i*HW];
        const float4* w4 = reinterpret_cast<const float4*>(swp + i*64);
#pragma unroll
        for (int o4 = 0; o4 < 16; o4++) {
            float4 w = w4[o4];
            acc[o4*4+0] += w.x*xi; acc[o4*4+1] += w.y*xi;
            acc[o4*4+2] += w.z*xi; acc[o4*4+3] += w.w*xi;
        }
    }
#pragma unroll
    for (int oc = 0; oc < 64; oc++) dst[oc*HW] = acc[oc];
}

__global__ void k_qkv(const float* __restrict__ x,  const float* __restrict__ y,
                      const float* __restrict__ qw, const float* __restrict__ qb,
                      const float* __restrict__ kw, const float* __restrict__ kb,
                      const float* __restrict__ vw, const float* __restrict__ vb) {
    __shared__ __align__(16) float sw[3*64*64];
    int tid = threadIdx.x;
    if (blockIdx.x == 0 && blockIdx.y == 0) {    // zero small accumulators
        for (int i = tid; i < BB*HEADS*CH*CH; i += 256) g_gram[i] = 0.f;
        for (int i = tid; i < BB*CC; i += 256) { g_qn[i] = 0.f; g_kn[i] = 0.f; }
    }
    for (int idx = tid; idx < 64*64; idx += 256) {
        int oc = idx >> 6, i = idx & 63;
        sw[0*4096 + i*64 + oc] = qw[idx];
        sw[1*4096 + i*64 + oc] = kw[idx];
        sw[2*4096 + i*64 + oc] = vw[idx];
    }
    __syncthreads();
    int b = blockIdx.y;
    int px = blockIdx.x*256 + tid;
    const float* xb = x + (size_t)b*CC*HW + px;
    const float* yb = y + (size_t)b*CC*HW + px;
    conv1x1_px(xb, sw + 0*4096, qb, g_q + (size_t)b*CC*HW + px);
    conv1x1_px(yb, sw + 1*4096, kb, g_k + (size_t)b*CC*HW + px);
    conv1x1_px(yb, sw + 2*4096, vb, g_v + (size_t)b*CC*HW + px);
}

// ---------------- gram + norms; extra grid slice preps conv weights --------
__global__ void k_gram(const float* __restrict__ w0, const float* __restrict__ w1,
                       const float* __restrict__ w2, const float* __restrict__ w3) {
    if (blockIdx.y == 32) {                      // weight prep: tf32 transpose
        const float* ws[4] = {w0, w1, w2, w3};
        int gtid = blockIdx.x*256 + threadIdx.x; // 0..8191
#pragma unroll
        for (int c = 0; c < 4; c++) {
            const float* wp = ws[c];
            for (int e = gtid; e < 9*64*64; e += 8192) {
                int tap = e >> 12, r = e & 4095;
                int ic = r >> 6, oc = r & 63;
                g_wbuf[c*36864 + tap*4096 + ic*64 + oc] =
                    to_tf32(wp[oc*576 + ic*9 + tap]);
            }
        }
        return;
    }
    __shared__ float qs[16*65];
    __shared__ float ks[16*65];
    int tid = threadIdx.x;
    int c = tid & 15, d = tid >> 4;
    int bh = blockIdx.y, b = bh >> 2, h = bh & 3;
    const float* qp = g_q + ((size_t)b*CC + h*CH)*HW;
    const float* kp = g_k + ((size_t)b*CC + h*CH)*HW;
    float acc = 0.f, nacc = 0.f;
    for (int t = 0; t < 32; t++) {
        int n0 = blockIdx.x*2048 + t*64;
        for (int idx = tid; idx < 1024; idx += 256) {
            int r = idx >> 6, j = idx & 63;
            qs[r*65 + j] = qp[(size_t)r*HW + n0 + j];
            ks[r*65 + j] = kp[(size_t)r*HW + n0 + j];
        }
        __syncthreads();
#pragma unroll 8
        for (int j = 0; j < 64; j++) acc += qs[c*65 + j] * ks[d*65 + j];
        if (d == 0) {
#pragma unroll 8
            for (int j = 0; j < 64; j++) { float v = qs[c*65 + j]; nacc += v*v; }
        } else if (d == 1) {
#pragma unroll 8
            for (int j = 0; j < 64; j++) { float v = ks[c*65 + j]; nacc += v*v; }
        }
        __syncthreads();
    }
    atomicAdd(&g_gram[bh*256 + c*16 + d], acc);
    if (d == 0) atomicAdd(&g_qn[b*CC + h*CH + c], nacc);
    if (d == 1) atomicAdd(&g_kn[b*CC + h*CH + c], nacc);
}

// ---------------- apply with per-block softmax recompute -------------------
__global__ void k_applysm() {
    __shared__ __align__(16) float sa[HEADS*CH*CH];
    int tid = threadIdx.x;
    int b = blockIdx.y;
    if (tid < 64) {                              // softmax rows (h, c)
        int h = tid >> 4, c = tid & 15;
        float nq = fmaxf(sqrtf(g_qn[b*CC + h*CH + c]), EPS);
        float l[16], m = -1e30f;
#pragma unroll
        for (int d = 0; d < 16; d++) {
            float nk = fmaxf(sqrtf(g_kn[b*CC + h*CH + d]), EPS);
            l[d] = g_gram[(b*4+h)*256 + c*16 + d] / (nq * nk);
            m = fmaxf(m, l[d]);
        }
        float s = 0.f;
#pragma unroll
        for (int d = 0; d < 16; d++) { l[d] = expf(l[d] - m); s += l[d]; }
        float inv = 1.f / s;
#pragma unroll
        for (int d = 0; d < 16; d++) sa[h*256 + c*16 + d] = l[d] * inv;
    }
    __syncthreads();
    int px = blockIdx.x*256 + tid;
    const float* vb = g_v  + (size_t)b*CC*HW + px;
    float*       ob = g_t0 + (size_t)b*CC*HW + px;
#pragma unroll
    for (int h = 0; h < 4; h++) {
        float vr[16];
#pragma unroll
        for (int d = 0; d < 16; d++) vr[d] = vb[(size_t)(h*CH + d)*HW];
#pragma unroll
        for (int c = 0; c < 16; c++) {
            const float4* a4 = reinterpret_cast<const float4*>(sa + h*256 + c*16);
            float s = 0.f;
#pragma unroll
            for (int d4 = 0; d4 < 4; d4++) {
                float4 a = a4[d4];
                s += a.x*vr[d4*4+0] + a.y*vr[d4*4+1] + a.z*vr[d4*4+2] + a.w*vr[d4*4+3];
            }
            ob[(size_t)(h*CH + c)*HW] = s;
        }
    }
}

// ---------------- 3x3 conv via tf32 mma.m16n8k8 ----------------------------
// Block 256 thr = 8 warps (4 m-warps x 2 n-halves). Output 64 oc x 128 px
// (32w x 4h). Weights pre-transposed tf32 in g_wbuf. Strides 232/72 (≡8 mod
// 32) give conflict-free A and B fragment LDS.
#define INS 232
#define WS  72
#define S_IN 0
#define S_W  (16*INS)                    /* 3712 */
#define SMEM_U32C (16*INS + 9*16*WS)     /* 14080 u32 = 56320 B */

__global__ void __launch_bounds__(256) k_conv3t(
        const float* __restrict__ in, const u32* __restrict__ wbuf,
        const float* __restrict__ bias, const float* __restrict__ skip,
        const float* __restrict__ skip2, float* __restrict__ out, int do_relu) {
    extern __shared__ __align__(16) u32 S[];
    int tid = threadIdx.x, lane = tid & 31, wid = tid >> 5;
    int wm = wid & 3, wn = wid >> 2;
    int t4 = lane & 3, g8 = lane >> 2;
    int b = blockIdx.z, gy0 = blockIdx.y*4, gx0 = blockIdx.x*32;
    const float* inb = in + (size_t)b*CC*HW;

    float acc[8][4];
#pragma unroll
    for (int j = 0; j < 8; j++)
#pragma unroll
        for (int r = 0; r < 4; r++) acc[j][r] = 0.f;

    int pb[8];
#pragma unroll
    for (int j = 0; j < 8; j++) {
        int px = wn*64 + j*8 + g8;
        pb[j] = (px >> 5)*34 + (px & 31);
    }

    for (int icb = 0; icb < 64; icb += 16) {
        // input tile [16 ic][6 y][34 x], tf32
        for (int i = tid; i < 16*204; i += 256) {
            int ic = i / 204, r = i - ic*204;
            int yy = r / 34, xx = r - yy*34;
            int iy = gy0 + yy - 1, ix = gx0 + xx - 1;
            float v = 0.f;
            if (iy >= 0 && iy < HH && ix >= 0 && ix < WW)
                v = inb[(size_t)(icb+ic)*HW + iy*WW + ix];
            S[S_IN + ic*INS + yy*34 + xx] = to_tf32(v);
        }
        // weight slab [9 tap][16 ic][oc pad 72], coalesced uint4 copy
        for (int i4 = tid; i4 < 2304; i4 += 256) {
            int oc4 = i4 & 15, r = i4 >> 4;
            int ic = r & 15, tap = r >> 4;
            uint4 v = *reinterpret_cast<const uint4*>(
                wbuf + tap*4096 + (icb+ic)*64 + oc4*4);
            *reinterpret_cast<uint4*>(S + S_W + (tap*16+ic)*WS + oc4*4) = v;
        }
        __syncthreads();

#pragma unroll 3
        for (int tap = 0; tap < 9; tap++) {
            int sh = (tap/3)*34 + (tap%3);
#pragma unroll
            for (int ks = 0; ks < 2; ks++) {
                int arow = S_W + (tap*16 + ks*8 + t4)*WS + wm*16 + g8;
                u32 a0 = S[arow],         a1 = S[arow + 8];
                u32 a2 = S[arow + 4*WS],  a3 = S[arow + 4*WS + 8];
                int ib = S_IN + (ks*8 + t4)*INS + sh;
#pragma unroll
                for (int j = 0; j < 8; j++) {
                    u32 b0 = S[ib + pb[j]];
                    u32 b1 = S[ib + 4*INS + pb[j]];
                    mma_tf32(acc[j], a0, a1, a2, a3, b0, b1);
                }
            }
        }
        __syncthreads();
    }

    // epilogue
#pragma unroll
    for (int j = 0; j < 8; j++) {
        int p  = wn*64 + j*8 + 2*t4;
        int py = p >> 5, px = p & 31;
        size_t rowidx = (size_t)b*CC*HW + (size_t)(gy0+py)*WW + gx0 + px;
#pragma unroll
        for (int mh = 0; mh < 2; mh++) {
            int oc = wm*16 + g8 + mh*8;
            size_t idx = rowidx + (size_t)oc*HW;
            float v0 = acc[j][mh*2+0] + __ldg(&bias[oc]);
            float v1 = acc[j][mh*2+1] + __ldg(&bias[oc]);
            if (do_relu) { v0 = fmaxf(v0, 0.f); v1 = fmaxf(v1, 0.f); }
            if (skip)  { v0 += skip[idx];  v1 += skip[idx+1]; }
            if (skip2) { v0 += skip2[idx]; v1 += skip2[idx+1]; }
            *reinterpret_cast<float2*>(&out[idx]) = make_float2(v0, v1);
        }
    }
}

// ---------------- launcher ---------------------------------------------------
extern "C" void kernel_launch(void* const* d_in, const int* in_sizes, int n_in,
                              void* d_out, int out_size) {
    const float* x    = (const float*)d_in[0];
    const float* y    = (const float*)d_in[1];
    const float* qw   = (const float*)d_in[2];
    const float* qb   = (const float*)d_in[3];
    const float* kw   = (const float*)d_in[4];
    const float* kb   = (const float*)d_in[5];
    const float* vw   = (const float*)d_in[6];
    const float* vb   = (const float*)d_in[7];
    const float* r1w1 = (const float*)d_in[8];
    const float* r1b1 = (const float*)d_in[9];
    const float* r1w2 = (const float*)d_in[10];
    const float* r1b2 = (const float*)d_in[11];
    const float* r2w1 = (const float*)d_in[12];
    const float* r2b1 = (const float*)d_in[13];
    const float* r2w2 = (const float*)d_in[14];
    const float* r2b2 = (const float*)d_in[15];
    float* outp = (float*)d_out;

    float *pq, *pk, *pt0; u32* pw;
    cudaGetSymbolAddress((void**)&pq,  g_q);
    cudaGetSymbolAddress((void**)&pk,  g_k);
    cudaGetSymbolAddress((void**)&pt0, g_t0);
    cudaGetSymbolAddress((void**)&pw,  g_wbuf);

    static int smem_set = 0;
    int smem_bytes = SMEM_U32C * 4;
    if (!smem_set) {
        cudaFuncSetAttribute(k_conv3t, cudaFuncAttributeMaxDynamicSharedMemorySize, smem_bytes);
        smem_set = 1;
    }

    k_qkv   <<<dim3(HW/256, BB), 256>>>(x, y, qw, qb, kw, kb, vw, vb);
    k_gram  <<<dim3(32, 33), 256>>>(r1w1, r1w2, r2w1, r2w2);
    k_applysm<<<dim3(HW/256, BB), 256>>>();

    dim3 cgrid(WW/32, HH/4, BB);
    k_conv3t<<<cgrid, 256, smem_bytes>>>(pt0, pw + 0*36864, r1b1, nullptr, nullptr, pq, 1);
    k_conv3t<<<cgrid, 256, smem_bytes>>>(pq,  pw + 1*36864, r1b2, pt0,     nullptr, pk, 0);
    k_conv3t<<<cgrid, 256, smem_bytes>>>(pk,  pw + 2*36864, r2b1, nullptr, nullptr, pq, 1);
    k_conv3t<<<cgrid, 256, smem_bytes>>>(pq,  pw + 3*36864, r2b2, pk,      y,       outp, 0);
}